// round 14
// baseline (speedup 1.0000x reference)
#include <cuda_runtime.h>
#include <cuda_bf16.h>
#include <math.h>
#include <stdint.h>

// Problem dims
#define BB   128
#define TT   512
#define FF   784
#define HH   256
#define NG   1024   // 4*H
#define CC   10
#define BN_EPS 1e-3f

// K1 GEMM tiling
#define BKC  16
#define NCHK (FF / BKC)   // 49

// Scratch (device globals; no runtime allocation allowed)
__device__ float  g_xw[(size_t)BB * TT * NG];    // 256 MiB
__device__ float  g_hs[(size_t)BB * TT * HH];    //  64 MiB
__device__ float4 g_rw[(size_t)HH * HH];         //   1 MiB packed rec weights {i,f,c,o}
__device__ __nv_bfloat16 g_bhi[(size_t)NG * FF]; // 1.6 MiB: kernel^T hi [n][k]
__device__ __nv_bfloat16 g_blo[(size_t)NG * FF]; // 1.6 MiB
__device__ __nv_bfloat16 g_ahi[(size_t)BB * TT * FF]; // 98 MiB: x hi [m][k]
__device__ __nv_bfloat16 g_alo[(size_t)BB * TT * FF]; // 98 MiB

// ---------------------------------------------------------------------------
// helpers
// ---------------------------------------------------------------------------
__device__ __forceinline__ uint32_t smem_u32(const void* p) {
    uint32_t a;
    asm("{ .reg .u64 t; cvta.to.shared.u64 t, %1; cvt.u32.u64 %0, t; }" : "=r"(a) : "l"(p));
    return a;
}
__device__ __forceinline__ void f2bf_hilo(float x, uint16_t& h, uint16_t& l) {
    __nv_bfloat16 hb = __float2bfloat16(x);
    h = __bfloat16_as_ushort(hb);
    l = __bfloat16_as_ushort(__float2bfloat16(x - __bfloat162float(hb)));
}
__device__ __forceinline__ float fsig(float x) {
    return __fdividef(1.f, 1.f + __expf(-x));
}
__device__ __forceinline__ float ftanh(float x) {
    x = fminf(fmaxf(x, -15.f), 15.f);
    float e = __expf(-2.f * x);
    return __fdividef(1.f - e, 1.f + e);
}
__device__ __forceinline__ void mma_bf16(float* d, const uint32_t* a, const uint32_t* b) {
    asm volatile(
        "mma.sync.aligned.m16n8k16.row.col.f32.bf16.bf16.f32 "
        "{%0,%1,%2,%3}, {%4,%5,%6,%7}, {%8,%9}, {%0,%1,%2,%3};"
        : "+f"(d[0]), "+f"(d[1]), "+f"(d[2]), "+f"(d[3])
        : "r"(a[0]), "r"(a[1]), "r"(a[2]), "r"(a[3]), "r"(b[0]), "r"(b[1]));
}
__device__ __forceinline__ void ldsm4(uint32_t* r, uint32_t a) {
    asm volatile("ldmatrix.sync.aligned.m8n8.x4.shared.b16 {%0,%1,%2,%3}, [%4];"
                 : "=r"(r[0]), "=r"(r[1]), "=r"(r[2]), "=r"(r[3]) : "r"(a));
}
// packed fp32x2 (B300 FFMA2)
__device__ __forceinline__ void ffma2(unsigned long long& d,
                                      unsigned long long a, unsigned long long b) {
    asm("fma.rn.f32x2 %0, %1, %2, %0;" : "+l"(d) : "l"(a), "l"(b));
}
__device__ __forceinline__ unsigned long long addx2(unsigned long long a,
                                                    unsigned long long b) {
    unsigned long long d;
    asm("add.rn.f32x2 %0, %1, %2;" : "=l"(d) : "l"(a), "l"(b));
    return d;
}
__device__ __forceinline__ unsigned long long shflx2(unsigned long long v, int m) {
    uint32_t lo = (uint32_t)v, hi = (uint32_t)(v >> 32);
    lo = __shfl_xor_sync(0xffffffffu, lo, m);
    hi = __shfl_xor_sync(0xffffffffu, hi, m);
    return ((unsigned long long)hi << 32) | lo;
}
__device__ __forceinline__ float lof(unsigned long long v) {
    return __uint_as_float((uint32_t)v);
}
__device__ __forceinline__ float hif(unsigned long long v) {
    return __uint_as_float((uint32_t)(v >> 32));
}
__device__ __forceinline__ void cp16(uint32_t dst, const void* src) {
    asm volatile("cp.async.cg.shared.global [%0], [%1], 16;" :: "r"(dst), "l"(src));
}
#define CP_COMMIT() asm volatile("cp.async.commit_group;" ::: "memory")
#define CP_WAIT2()  asm volatile("cp.async.wait_group 2;"  ::: "memory")

// ---------------------------------------------------------------------------
// K0a: pack rec_kernel [H,4H] -> rw[k][u] float4 {i,f,c,o}
// ---------------------------------------------------------------------------
__global__ void pack_rec_kernel(const float* __restrict__ rec, float4* __restrict__ rw)
{
    int idx = blockIdx.x * blockDim.x + threadIdx.x;
    if (idx >= HH * HH) return;
    int k = idx >> 8;
    int u = idx & 255;
    const float* r = rec + (size_t)k * NG;
    rw[idx] = make_float4(r[u], r[HH + u], r[2 * HH + u], r[3 * HH + u]);
}

// ---------------------------------------------------------------------------
// K0b: split + transpose kernel [F,4H] -> g_bhi/g_blo [n][k] bf16
// ---------------------------------------------------------------------------
__global__ void pack_b_kernel(const float* __restrict__ Bm)
{
    int idx = blockIdx.x * blockDim.x + threadIdx.x;
    if (idx >= NG * FF) return;
    int n = idx / FF;
    int k = idx % FF;
    float v = Bm[(size_t)k * NG + n];
    uint16_t h, l;
    f2bf_hilo(v, h, l);
    g_bhi[idx] = __ushort_as_bfloat16(h);
    g_blo[idx] = __ushort_as_bfloat16(l);
}

// ---------------------------------------------------------------------------
// K0c: split x [m][k] fp32 -> g_ahi/g_alo bf16 (same layout)
// ---------------------------------------------------------------------------
__global__ void pack_a_kernel(const float* __restrict__ x)
{
    size_t idx = (size_t)blockIdx.x * blockDim.x + threadIdx.x;
    if (idx >= (size_t)BB * TT * FF) return;
    float v = x[idx];
    uint16_t h, l;
    f2bf_hilo(v, h, l);
    g_ahi[idx] = __ushort_as_bfloat16(h);
    g_alo[idx] = __ushort_as_bfloat16(l);
}

// ---------------------------------------------------------------------------
// K1: xw = x @ kernel + bias via mma.sync bf16x3, pre-packed bf16 A/B,
// 4-stage cp.async pipeline, ldmatrix.x4 fragment loads. (unchanged R12)
// ---------------------------------------------------------------------------
#define SROW 48
#define K1_STAGE_BYTES (4 * 128 * SROW)              // 24576
#define K1_SMEM (4 * K1_STAGE_BYTES)                 // 98304

__global__ __launch_bounds__(256, 2)
void gemm_mma_kernel(const float* __restrict__ bias)
{
    extern __shared__ __align__(16) char smk[];
    const uint32_t sbase = smem_u32(smk);

    const int tid  = threadIdx.x;
    const int lane = tid & 31;
    const int wid  = tid >> 5;
    const int bx   = blockIdx.x;
    const int by   = blockIdx.y;

    const int m0w = (wid & 3) * 32;
    const int n0w = (wid >> 2) * 64;
    const int g   = lane >> 2;
    const int tq  = lane & 3;

    float d[2][8][4];
#pragma unroll
    for (int i = 0; i < 2; i++)
#pragma unroll
        for (int j = 0; j < 8; j++)
#pragma unroll
            for (int q = 0; q < 4; q++) d[i][j][q] = 0.f;

    const int r = tid >> 1;
    const int c = tid & 1;
    const size_t a_row_bytes = ((size_t)(by * 128 + r) * FF) * 2 + c * 16;
    const size_t b_row_bytes = ((size_t)(bx * 128 + r) * FF) * 2 + c * 16;
    const char* pAh = (const char*)g_ahi + a_row_bytes;
    const char* pAl = (const char*)g_alo + a_row_bytes;
    const char* pBh = (const char*)g_bhi + b_row_bytes;
    const char* pBl = (const char*)g_blo + b_row_bytes;
    const uint32_t s_off = (uint32_t)(r * SROW + c * 16);

    uint32_t a_off[2], b_off[4];
#pragma unroll
    for (int i = 0; i < 2; i++)
        a_off[i] = (uint32_t)((m0w + i * 16 + (lane & 15)) * SROW + (lane >> 4) * 16);
#pragma unroll
    for (int j2 = 0; j2 < 4; j2++)
        b_off[j2] = (uint32_t)((n0w + j2 * 16 + ((lane >> 4) * 8) + (lane & 7)) * SROW
                               + ((lane >> 3) & 1) * 16);

#pragma unroll
    for (int s = 0; s < 3; s++) {
        const uint32_t sb = sbase + s * K1_STAGE_BYTES;
        const size_t gk = (size_t)s * 32;
        cp16(sb + s_off,              pAh + gk);
        cp16(sb + 6144  + s_off,      pAl + gk);
        cp16(sb + 12288 + s_off,      pBh + gk);
        cp16(sb + 18432 + s_off,      pBl + gk);
        CP_COMMIT();
    }

    for (int ic = 0; ic < NCHK; ic++) {
        CP_WAIT2();
        __syncthreads();

        {
            const int s = ic + 3;
            if (s < NCHK) {
                const uint32_t sb = sbase + (s & 3) * K1_STAGE_BYTES;
                const size_t gk = (size_t)s * 32;
                cp16(sb + s_off,         pAh + gk);
                cp16(sb + 6144  + s_off, pAl + gk);
                cp16(sb + 12288 + s_off, pBh + gk);
                cp16(sb + 18432 + s_off, pBl + gk);
            }
            CP_COMMIT();
        }

        const uint32_t stg = sbase + (ic & 3) * K1_STAGE_BYTES;

        uint32_t ah[2][4], al[2][4];
#pragma unroll
        for (int i = 0; i < 2; i++) {
            ldsm4(ah[i], stg + a_off[i]);
            ldsm4(al[i], stg + 6144 + a_off[i]);
        }

#pragma unroll
        for (int j2 = 0; j2 < 4; j2++) {
            uint32_t bh4[4], bl4[4];
            ldsm4(bh4, stg + 12288 + b_off[j2]);
            ldsm4(bl4, stg + 18432 + b_off[j2]);
#pragma unroll
            for (int jj = 0; jj < 2; jj++) {
                const int j = j2 * 2 + jj;
                uint32_t bhf[2] = {bh4[jj * 2], bh4[jj * 2 + 1]};
                uint32_t blf[2] = {bl4[jj * 2], bl4[jj * 2 + 1]};
#pragma unroll
                for (int i = 0; i < 2; i++) {
                    mma_bf16(d[i][j], ah[i], bhf);
                    mma_bf16(d[i][j], ah[i], blf);
                    mma_bf16(d[i][j], al[i], bhf);
                }
            }
        }
    }

#pragma unroll
    for (int j = 0; j < 8; j++) {
        const int col = bx * 128 + n0w + j * 8 + tq * 2;
        const float b0 = bias[col];
        const float b1 = bias[col + 1];
#pragma unroll
        for (int i = 0; i < 2; i++) {
            const int row = by * 128 + m0w + i * 16 + g;
            float2 v0 = make_float2(d[i][j][0] + b0, d[i][j][1] + b1);
            float2 v1 = make_float2(d[i][j][2] + b0, d[i][j][3] + b1);
            *(float2*)(g_xw + (size_t)row * NG + col)       = v0;
            *(float2*)(g_xw + (size_t)(row + 8) * NG + col) = v1;
        }
    }
}

// ---------------------------------------------------------------------------
// K2: peephole LSTM — 32 clusters x 4 CTAs, 4 batches/cluster,
// LANE-LEVEL k-split (no intra-CTA sync in the step loop):
//   warp w owns units [w*8, w*8+8); lane = (u8 = lane>>2, kq = lane&3).
//   Lane accumulates unit (w*8+u8)'s gate pairs over k-quarter kq for all
//   4 batches (FFMA2). Reduction over kq = 2 shfl_xor rounds. Lane kq doubles
//   as batch index for gate math + DSMEM h publish. Only sync per step is
//   the split cluster arrive/wait.
// Weights: 44 k/quarter in smem (176 KB) + 20 k/quarter in persistent regs.
// ---------------------------------------------------------------------------
#define K2_CLU   4
#define K2_BATCH 4
#define K2_KS    44
#define K2_KR    20
#define K2_WSB   (4 * K2_KS * 64 * 16)           // 180224
#define K2_H2SZ  16384                           // [2][256 k][4 b] dup-ull
#define K2_SMEM  (K2_WSB + K2_H2SZ)              // 196608

__global__ __launch_bounds__(256, 1) __cluster_dims__(K2_CLU, 1, 1)
void lstm_lane_kernel(const float*  __restrict__ xw,
                      const float4* __restrict__ rw,
                      const float*  __restrict__ wci_p,
                      const float*  __restrict__ wcf_p,
                      const float*  __restrict__ wco_p,
                      float* __restrict__ hs)
{
    extern __shared__ __align__(16) char sm2[];
    char* wsm = sm2;                       // [kq*44 + kk][64 ul] ull2
    char* h2  = sm2 + K2_WSB;              // [2][256 k][4 b] dup-ull

    const int tid = threadIdx.x;
    uint32_t rank;
    asm("mov.u32 %0, %%cluster_ctarank;" : "=r"(rank));
    const int cl = blockIdx.x >> 2;
    const int b0 = cl * K2_BATCH;

    const int w    = tid >> 5;
    const int lane = tid & 31;
    const int u8   = lane >> 2;          // unit within warp (0..7)
    const int kq   = lane & 3;           // k-quarter == batch owned
    const int ul   = w * 8 + u8;         // unit within CTA (0..63)
    const int uc   = (int)rank * 64 + ul;
    const int ug   = uc;                 // global unit (same)
    const int cb   = kq;                 // batch owned by this lane

    // stage smem weights: [tier*44 + kk][64 units]
    for (int idx = tid; idx < 4 * K2_KS * 64; idx += 256) {
        int kp = idx >> 6;
        int uu = idx & 63;
        int tier = kp / K2_KS;
        int kk   = kp - tier * K2_KS;
        int kglob = tier * 64 + kk;
        *(float4*)(wsm + (size_t)idx * 16) = rw[(kglob << 8) + (int)rank * 64 + uu];
    }
    // zero h buffer 0
    for (int i = tid; i < 1024; i += 256)
        *(unsigned long long*)(h2 + (size_t)i * 8) = 0ull;

    const float wci = wci_p[uc];
    const float wcf = wcf_p[uc];
    const float wco = wco_p[uc];

    uint32_t rem[K2_CLU];
    {
        uint32_t l0 = smem_u32(h2) + (uint32_t)(uc * 4 + cb) * 8u;
#pragma unroll
        for (int r2 = 0; r2 < K2_CLU; r2++)
            asm("mapa.shared::cluster.u32 %0, %1, %2;"
                : "=r"(rem[r2]) : "r"(l0), "r"(r2));
    }

    // persistent register weights: k = kq*64 + 44 + j  for unit ug
    ulonglong2 wper[K2_KR];
#pragma unroll
    for (int j = 0; j < K2_KR; j++)
        wper[j] = *(const ulonglong2*)((const char*)(rw + (size_t)(kq * 64 + K2_KS + j) * HH + ug));

    __syncthreads();
    asm volatile("barrier.cluster.arrive.aligned;" ::: "memory");
    asm volatile("barrier.cluster.wait.aligned;"   ::: "memory");

    const char* wp_s = wsm + ((size_t)(kq * K2_KS) * 64 + ul) * 16;  // k-stride 1024 B
    const float* xc = xw + (size_t)(b0 + cb) * TT * NG;
    float* hc = hs + (size_t)(b0 + cb) * TT * HH + uc;

    float cstate = 0.f;

    for (int t = 0; t < TT; t++) {
        const int rb = t & 1;

        // this step's gate inputs — independent of h(t), issued before wait
        float xv0 = xc[uc];
        float xv1 = xc[HH + uc];
        float xv2 = xc[2 * HH + uc];
        float xv3 = xc[3 * HH + uc];

        if (t > 0)
            asm volatile("barrier.cluster.wait.aligned;" ::: "memory");

        // accumulate 4 batches x {(i,f),(c,o)} over this lane's k-quarter
        unsigned long long aif[4], aco[4];
#pragma unroll
        for (int b2 = 0; b2 < 4; b2++) { aif[b2] = 0ull; aco[b2] = 0ull; }

        const char* hq = h2 + rb * (K2_H2SZ / 2) + (kq * 64) * 32;

        // smem tier: k = kq*64 + [0,44)
#pragma unroll 4
        for (int kk = 0; kk < K2_KS; kk++) {
            ulonglong2 wv = *(const ulonglong2*)(wp_s + (size_t)kk * 1024);
            const char* hh = hq + kk * 32;
            ulonglong2 h01 = *(const ulonglong2*)(hh);
            ulonglong2 h23 = *(const ulonglong2*)(hh + 16);
            ffma2(aif[0], wv.x, h01.x); ffma2(aco[0], wv.y, h01.x);
            ffma2(aif[1], wv.x, h01.y); ffma2(aco[1], wv.y, h01.y);
            ffma2(aif[2], wv.x, h23.x); ffma2(aco[2], wv.y, h23.x);
            ffma2(aif[3], wv.x, h23.y); ffma2(aco[3], wv.y, h23.y);
        }
        // register tier: k = kq*64 + [44,64)
#pragma unroll
        for (int j = 0; j < K2_KR; j++) {
            ulonglong2 wv = wper[j];
            const char* hh = hq + (K2_KS + j) * 32;
            ulonglong2 h01 = *(const ulonglong2*)(hh);
            ulonglong2 h23 = *(const ulonglong2*)(hh + 16);
            ffma2(aif[0], wv.x, h01.x); ffma2(aco[0], wv.y, h01.x);
            ffma2(aif[1], wv.x, h01.y); ffma2(aco[1], wv.y, h01.y);
            ffma2(aif[2], wv.x, h23.x); ffma2(aco[2], wv.y, h23.x);
            ffma2(aif[3], wv.x, h23.y); ffma2(aco[3], wv.y, h23.y);
        }

        // reduce over the 4 k-quarters (lanes differing in bits 0-1)
#pragma unroll
        for (int b2 = 0; b2 < 4; b2++) {
            aif[b2] = addx2(aif[b2], shflx2(aif[b2], 1));
            aif[b2] = addx2(aif[b2], shflx2(aif[b2], 2));
            aco[b2] = addx2(aco[b2], shflx2(aco[b2], 1));
            aco[b2] = addx2(aco[b2], shflx2(aco[b2], 2));
        }

        // gate math for this lane's cell (unit uc, batch cb = kq)
        float zi = lof(aif[cb]), zf = hif(aif[cb]);
        float zc = lof(aco[cb]), zo = hif(aco[cb]);

        float ig = fsig(zi + xv0 + cstate * wci);
        float fg = fsig(zf + xv1 + cstate * wcf);
        float cn = fg * cstate + ig * ftanh(zc + xv2);
        float og = fsig(zo + xv3 + cn * wco);
        float hn = og * ftanh(cn);
        cstate = cn;

        // publish h (dup pair) into write buffer of all 4 CTAs
        unsigned long long hdup;
        asm("mov.b64 %0, {%1, %1};" : "=l"(hdup) : "r"(__float_as_uint(hn)));
        const uint32_t wboff = (uint32_t)((rb ^ 1) * (K2_H2SZ / 2));
#pragma unroll
        for (int r2 = 0; r2 < K2_CLU; r2++)
            asm volatile("st.shared::cluster.b64 [%0], %1;"
                         :: "r"(rem[r2] + wboff), "l"(hdup) : "memory");

        hc[0] = hn;
        hc += HH;
        xc += NG;

        asm volatile("barrier.cluster.arrive.aligned;" ::: "memory");
    }
    asm volatile("barrier.cluster.wait.aligned;" ::: "memory");
}

// ---------------------------------------------------------------------------
// K3: BN(inference) -> tanh -> dense head.
// ---------------------------------------------------------------------------
__global__ __launch_bounds__(256)
void head_kernel(const float* __restrict__ hs,
                 const float* __restrict__ gamma,
                 const float* __restrict__ beta,
                 const float* __restrict__ mean,
                 const float* __restrict__ var,
                 const float* __restrict__ fc,
                 float* __restrict__ out)
{
    const int warp = (blockIdx.x * blockDim.x + threadIdx.x) >> 5;
    const int lane = threadIdx.x & 31;
    if (warp >= BB * TT) return;

    const float* hrow = hs + (size_t)warp * HH;
    float acc[CC];
#pragma unroll
    for (int c = 0; c < CC; c++) acc[c] = 0.f;

#pragma unroll
    for (int kk = 0; kk < HH / 32; kk++) {
        int k = kk * 32 + lane;
        float s = rsqrtf(var[k] + BN_EPS) * gamma[k];
        float v = tanhf((hrow[k] - mean[k]) * s + beta[k]);
#pragma unroll
        for (int c = 0; c < CC; c++)
            acc[c] += v * fc[k * CC + c];
    }
#pragma unroll
    for (int c = 0; c < CC; c++) {
#pragma unroll
        for (int off = 16; off > 0; off >>= 1)
            acc[c] += __shfl_xor_sync(0xffffffffu, acc[c], off);
    }
    if (lane == 0) {
        float* orow = out + (size_t)warp * CC;
#pragma unroll
        for (int c = 0; c < CC; c++) orow[c] = acc[c];
    }
}

// ---------------------------------------------------------------------------
extern "C" void kernel_launch(void* const* d_in, const int* in_sizes, int n_in,
                              void* d_out, int out_size)
{
    const float* x      = (const float*)d_in[0];
    const float* kernel = (const float*)d_in[1];
    const float* rec    = (const float*)d_in[2];
    const float* bias   = (const float*)d_in[3];
    const float* w_ci   = (const float*)d_in[4];
    const float* w_cf   = (const float*)d_in[5];
    const float* w_co   = (const float*)d_in[6];
    const float* gamma  = (const float*)d_in[7];
    const float* beta   = (const float*)d_in[8];
    const float* mmean  = (const float*)d_in[9];
    const float* mvar   = (const float*)d_in[10];
    const float* fc_w   = (const float*)d_in[11];
    float* out = (float*)d_out;

    float*  xw_p;
    float*  hs_p;
    float4* rw_p;
    cudaGetSymbolAddress((void**)&xw_p, g_xw);
    cudaGetSymbolAddress((void**)&hs_p, g_hs);
    cudaGetSymbolAddress((void**)&rw_p, g_rw);

    cudaFuncSetAttribute(gemm_mma_kernel,
                         cudaFuncAttributeMaxDynamicSharedMemorySize, K1_SMEM);
    cudaFuncSetAttribute(lstm_lane_kernel,
                         cudaFuncAttributeMaxDynamicSharedMemorySize, K2_SMEM);

    // K0: packing
    pack_rec_kernel<<<(HH * HH + 255) / 256, 256>>>(rec, rw_p);
    pack_b_kernel<<<((size_t)NG * FF + 255) / 256, 256>>>(kernel);
    pack_a_kernel<<<(unsigned)(((size_t)BB * TT * FF + 255) / 256), 256>>>(x);

    // K1: cp.async-pipelined HMMA GEMM with ldmatrix fragments
    dim3 g1(NG / 128, (BB * TT) / 128);
    gemm_mma_kernel<<<g1, 256, K1_SMEM>>>(bias);

    // K2: recurrence, lane-level k-split (no intra-CTA sync per step)
    lstm_lane_kernel<<<(BB / K2_BATCH) * K2_CLU, 256, K2_SMEM>>>(
        xw_p, rw_p, w_ci, w_cf, w_co, hs_p);

    // K3: head
    int rows = BB * TT;
    head_kernel<<<(rows * 32 + 255) / 256, 256>>>(hs_p, gamma, beta, mmean, mvar, fc_w, out);
}

// round 15
// speedup vs baseline: 2.5408x; 2.5408x over previous
#include <cuda_runtime.h>
#include <cuda_bf16.h>
#include <math.h>
#include <stdint.h>

// Problem dims
#define BB   128
#define TT   512
#define FF   784
#define HH   256
#define NG   1024   // 4*H
#define CC   10
#define BN_EPS 1e-3f

// K1 GEMM tiling
#define BKC  16
#define NCHK (FF / BKC)   // 49

// Scratch (device globals; no runtime allocation allowed)
__device__ float  g_xw[(size_t)BB * TT * NG];    // 256 MiB
__device__ float  g_hs[(size_t)BB * TT * HH];    //  64 MiB
__device__ float4 g_rw[(size_t)HH * HH];         //   1 MiB packed rec weights {i,f,c,o}
__device__ __nv_bfloat16 g_bhi[(size_t)NG * FF]; // 1.6 MiB: kernel^T hi [n][k]
__device__ __nv_bfloat16 g_blo[(size_t)NG * FF]; // 1.6 MiB
__device__ __nv_bfloat16 g_ahi[(size_t)BB * TT * FF]; // 98 MiB: x hi [m][k]
__device__ __nv_bfloat16 g_alo[(size_t)BB * TT * FF]; // 98 MiB

// ---------------------------------------------------------------------------
// helpers
// ---------------------------------------------------------------------------
__device__ __forceinline__ uint32_t smem_u32(const void* p) {
    uint32_t a;
    asm("{ .reg .u64 t; cvta.to.shared.u64 t, %1; cvt.u32.u64 %0, t; }" : "=r"(a) : "l"(p));
    return a;
}
__device__ __forceinline__ void f2bf_hilo(float x, uint16_t& h, uint16_t& l) {
    __nv_bfloat16 hb = __float2bfloat16(x);
    h = __bfloat16_as_ushort(hb);
    l = __bfloat16_as_ushort(__float2bfloat16(x - __bfloat162float(hb)));
}
__device__ __forceinline__ float fsig(float x) {
    return __fdividef(1.f, 1.f + __expf(-x));
}
__device__ __forceinline__ float ftanh(float x) {
    x = fminf(fmaxf(x, -15.f), 15.f);
    float e = __expf(-2.f * x);
    return __fdividef(1.f - e, 1.f + e);
}
__device__ __forceinline__ void mma_bf16(float* d, const uint32_t* a, const uint32_t* b) {
    asm volatile(
        "mma.sync.aligned.m16n8k16.row.col.f32.bf16.bf16.f32 "
        "{%0,%1,%2,%3}, {%4,%5,%6,%7}, {%8,%9}, {%0,%1,%2,%3};"
        : "+f"(d[0]), "+f"(d[1]), "+f"(d[2]), "+f"(d[3])
        : "r"(a[0]), "r"(a[1]), "r"(a[2]), "r"(a[3]), "r"(b[0]), "r"(b[1]));
}
__device__ __forceinline__ void ldsm4(uint32_t* r, uint32_t a) {
    asm volatile("ldmatrix.sync.aligned.m8n8.x4.shared.b16 {%0,%1,%2,%3}, [%4];"
                 : "=r"(r[0]), "=r"(r[1]), "=r"(r[2]), "=r"(r[3]) : "r"(a));
}
// packed fp32x2 (B300 FFMA2)
__device__ __forceinline__ void ffma2(unsigned long long& d,
                                      unsigned long long a, unsigned long long b) {
    asm("fma.rn.f32x2 %0, %1, %2, %0;" : "+l"(d) : "l"(a), "l"(b));
}
__device__ __forceinline__ unsigned long long addx2(unsigned long long a,
                                                    unsigned long long b) {
    unsigned long long d;
    asm("add.rn.f32x2 %0, %1, %2;" : "=l"(d) : "l"(a), "l"(b));
    return d;
}
__device__ __forceinline__ float lof(unsigned long long v) {
    return __uint_as_float((uint32_t)v);
}
__device__ __forceinline__ float hif(unsigned long long v) {
    return __uint_as_float((uint32_t)(v >> 32));
}
__device__ __forceinline__ void cp16(uint32_t dst, const void* src) {
    asm volatile("cp.async.cg.shared.global [%0], [%1], 16;" :: "r"(dst), "l"(src));
}
#define CP_COMMIT() asm volatile("cp.async.commit_group;" ::: "memory")
#define CP_WAIT2()  asm volatile("cp.async.wait_group 2;"  ::: "memory")

// ---------------------------------------------------------------------------
// K0a: pack rec_kernel [H,4H] -> rw[k][u] float4 {i,f,c,o}
// ---------------------------------------------------------------------------
__global__ void pack_rec_kernel(const float* __restrict__ rec, float4* __restrict__ rw)
{
    int idx = blockIdx.x * blockDim.x + threadIdx.x;
    if (idx >= HH * HH) return;
    int k = idx >> 8;
    int u = idx & 255;
    const float* r = rec + (size_t)k * NG;
    rw[idx] = make_float4(r[u], r[HH + u], r[2 * HH + u], r[3 * HH + u]);
}

// ---------------------------------------------------------------------------
// K0b: split + transpose kernel [F,4H] -> g_bhi/g_blo [n][k] bf16
// ---------------------------------------------------------------------------
__global__ void pack_b_kernel(const float* __restrict__ Bm)
{
    int idx = blockIdx.x * blockDim.x + threadIdx.x;
    if (idx >= NG * FF) return;
    int n = idx / FF;
    int k = idx % FF;
    float v = Bm[(size_t)k * NG + n];
    uint16_t h, l;
    f2bf_hilo(v, h, l);
    g_bhi[idx] = __ushort_as_bfloat16(h);
    g_blo[idx] = __ushort_as_bfloat16(l);
}

// ---------------------------------------------------------------------------
// K0c: split x [m][k] fp32 -> g_ahi/g_alo bf16 (same layout)
// ---------------------------------------------------------------------------
__global__ void pack_a_kernel(const float* __restrict__ x)
{
    size_t idx = (size_t)blockIdx.x * blockDim.x + threadIdx.x;
    if (idx >= (size_t)BB * TT * FF) return;
    float v = x[idx];
    uint16_t h, l;
    f2bf_hilo(v, h, l);
    g_ahi[idx] = __ushort_as_bfloat16(h);
    g_alo[idx] = __ushort_as_bfloat16(l);
}

// ---------------------------------------------------------------------------
// K1: xw = x @ kernel + bias via mma.sync bf16x3, pre-packed bf16 A/B,
// 4-stage cp.async pipeline, ldmatrix.x4 fragments.
// R15 change: term-major MMA ordering inside each j2 block — dependent MMAs
// on the same accumulator are spaced 4 apart instead of back-to-back.
// Per-accumulator add order (hh, hl, lh) is preserved -> bitwise identical.
// ---------------------------------------------------------------------------
#define SROW 48
#define K1_STAGE_BYTES (4 * 128 * SROW)              // 24576
#define K1_SMEM (4 * K1_STAGE_BYTES)                 // 98304

__global__ __launch_bounds__(256, 2)
void gemm_mma_kernel(const float* __restrict__ bias)
{
    extern __shared__ __align__(16) char smk[];
    const uint32_t sbase = smem_u32(smk);

    const int tid  = threadIdx.x;
    const int lane = tid & 31;
    const int wid  = tid >> 5;
    const int bx   = blockIdx.x;
    const int by   = blockIdx.y;

    const int m0w = (wid & 3) * 32;
    const int n0w = (wid >> 2) * 64;
    const int g   = lane >> 2;
    const int tq  = lane & 3;

    float d[2][8][4];
#pragma unroll
    for (int i = 0; i < 2; i++)
#pragma unroll
        for (int j = 0; j < 8; j++)
#pragma unroll
            for (int q = 0; q < 4; q++) d[i][j][q] = 0.f;

    const int r = tid >> 1;
    const int c = tid & 1;
    const size_t a_row_bytes = ((size_t)(by * 128 + r) * FF) * 2 + c * 16;
    const size_t b_row_bytes = ((size_t)(bx * 128 + r) * FF) * 2 + c * 16;
    const char* pAh = (const char*)g_ahi + a_row_bytes;
    const char* pAl = (const char*)g_alo + a_row_bytes;
    const char* pBh = (const char*)g_bhi + b_row_bytes;
    const char* pBl = (const char*)g_blo + b_row_bytes;
    const uint32_t s_off = (uint32_t)(r * SROW + c * 16);

    uint32_t a_off[2], b_off[4];
#pragma unroll
    for (int i = 0; i < 2; i++)
        a_off[i] = (uint32_t)((m0w + i * 16 + (lane & 15)) * SROW + (lane >> 4) * 16);
#pragma unroll
    for (int j2 = 0; j2 < 4; j2++)
        b_off[j2] = (uint32_t)((n0w + j2 * 16 + ((lane >> 4) * 8) + (lane & 7)) * SROW
                               + ((lane >> 3) & 1) * 16);

#pragma unroll
    for (int s = 0; s < 3; s++) {
        const uint32_t sb = sbase + s * K1_STAGE_BYTES;
        const size_t gk = (size_t)s * 32;
        cp16(sb + s_off,              pAh + gk);
        cp16(sb + 6144  + s_off,      pAl + gk);
        cp16(sb + 12288 + s_off,      pBh + gk);
        cp16(sb + 18432 + s_off,      pBl + gk);
        CP_COMMIT();
    }

    for (int ic = 0; ic < NCHK; ic++) {
        CP_WAIT2();
        __syncthreads();

        {
            const int s = ic + 3;
            if (s < NCHK) {
                const uint32_t sb = sbase + (s & 3) * K1_STAGE_BYTES;
                const size_t gk = (size_t)s * 32;
                cp16(sb + s_off,         pAh + gk);
                cp16(sb + 6144  + s_off, pAl + gk);
                cp16(sb + 12288 + s_off, pBh + gk);
                cp16(sb + 18432 + s_off, pBl + gk);
            }
            CP_COMMIT();
        }

        const uint32_t stg = sbase + (ic & 3) * K1_STAGE_BYTES;

        uint32_t ah[2][4], al[2][4];
#pragma unroll
        for (int i = 0; i < 2; i++) {
            ldsm4(ah[i], stg + a_off[i]);
            ldsm4(al[i], stg + 6144 + a_off[i]);
        }

#pragma unroll
        for (int j2 = 0; j2 < 4; j2++) {
            uint32_t bh4[4], bl4[4];
            ldsm4(bh4, stg + 12288 + b_off[j2]);
            ldsm4(bl4, stg + 18432 + b_off[j2]);

            // term 1: ah x bh for all 4 accumulators of this j2 block
#pragma unroll
            for (int jj = 0; jj < 2; jj++) {
                uint32_t bhf[2] = {bh4[jj * 2], bh4[jj * 2 + 1]};
#pragma unroll
                for (int i = 0; i < 2; i++)
                    mma_bf16(d[i][j2 * 2 + jj], ah[i], bhf);
            }
            // term 2: ah x bl
#pragma unroll
            for (int jj = 0; jj < 2; jj++) {
                uint32_t blf[2] = {bl4[jj * 2], bl4[jj * 2 + 1]};
#pragma unroll
                for (int i = 0; i < 2; i++)
                    mma_bf16(d[i][j2 * 2 + jj], ah[i], blf);
            }
            // term 3: al x bh
#pragma unroll
            for (int jj = 0; jj < 2; jj++) {
                uint32_t bhf[2] = {bh4[jj * 2], bh4[jj * 2 + 1]};
#pragma unroll
                for (int i = 0; i < 2; i++)
                    mma_bf16(d[i][j2 * 2 + jj], al[i], bhf);
            }
        }
    }

#pragma unroll
    for (int j = 0; j < 8; j++) {
        const int col = bx * 128 + n0w + j * 8 + tq * 2;
        const float b0 = bias[col];
        const float b1 = bias[col + 1];
#pragma unroll
        for (int i = 0; i < 2; i++) {
            const int row = by * 128 + m0w + i * 16 + g;
            float2 v0 = make_float2(d[i][j][0] + b0, d[i][j][1] + b1);
            float2 v1 = make_float2(d[i][j][2] + b0, d[i][j][3] + b1);
            *(float2*)(g_xw + (size_t)row * NG + col)       = v0;
            *(float2*)(g_xw + (size_t)(row + 8) * NG + col) = v1;
        }
    }
}

// ---------------------------------------------------------------------------
// K2: peephole LSTM — exact R12 version (best known).
// 32 clusters x 4 CTAs (128 SMs), 4 batches/cluster, k-split-4,
// three-tier weight residency:
//   ks 0,1 : k [0,128)   smem
//   ks 2   : k [128,176) smem + k [176,192) persistent registers
//   ks 3   : k [192,256) streamed from L2 (reg double-buffer; chunk-0
//            reloaded during the cell phase)
// ---------------------------------------------------------------------------
#define K2_CLU   4
#define K2_BATCH 4
#define K2_WSB   (176 * 64 * 16)                 // 180224
#define K2_H2SZ  16384
#define K2_PART  16384
#define K2_SMEM  (K2_WSB + K2_H2SZ + K2_PART)    // 212992

__global__ __launch_bounds__(256, 1) __cluster_dims__(K2_CLU, 1, 1)
void lstm_hyb_kernel(const float*  __restrict__ xw,
                     const float4* __restrict__ rw,
                     const float*  __restrict__ wci_p,
                     const float*  __restrict__ wcf_p,
                     const float*  __restrict__ wco_p,
                     float* __restrict__ hs)
{
    extern __shared__ __align__(16) char sm2[];
    char* wsm  = sm2;                       // [k<176][64 ul] ull2
    char* h2   = sm2 + K2_WSB;              // [2][256 k][4 b] dup-ull
    char* part = sm2 + K2_WSB + K2_H2SZ;    // [4 b][4 ks][64 ul] ull2

    const int tid = threadIdx.x;
    uint32_t rank;
    asm("mov.u32 %0, %%cluster_ctarank;" : "=r"(rank));
    const int cl = blockIdx.x >> 2;
    const int b0 = cl * K2_BATCH;

    const int ks = tid >> 6;
    const int ul = tid & 63;
    const int ug = (int)rank * 64 + ul;
    const int cu = tid >> 2;
    const int cb = tid & 3;
    const int uc = (int)rank * 64 + cu;

    // stage k<176 weights
    for (int idx = tid; idx < 176 * 64; idx += 256) {
        int k  = idx >> 6;
        int uu = idx & 63;
        *(float4*)(wsm + (size_t)idx * 16) = rw[(k << 8) + (int)rank * 64 + uu];
    }
    for (int i = tid; i < 1024; i += 256)
        *(unsigned long long*)(h2 + (size_t)i * 8) = 0ull;

    const float wci = wci_p[uc];
    const float wcf = wcf_p[uc];
    const float wco = wco_p[uc];

    uint32_t rem[K2_CLU];
    {
        uint32_t l0 = smem_u32(h2) + (uint32_t)(uc * 4 + cb) * 8u;
#pragma unroll
        for (int r2 = 0; r2 < K2_CLU; r2++)
            asm("mapa.shared::cluster.u32 %0, %1, %2;"
                : "=r"(rem[r2]) : "r"(l0), "r"(r2));
    }

    __syncthreads();
    asm volatile("barrier.cluster.arrive.aligned;" ::: "memory");
    asm volatile("barrier.cluster.wait.aligned;"   ::: "memory");

    const char* wp_s = wsm + ((size_t)(ks * 64) * 64 + ul) * 16;
    const char* wp_g = (const char*)(rw + (size_t)(ks * 64) * HH + ug);
    const float* xc = xw + (size_t)(b0 + cb) * TT * NG;
    float* hc = hs + (size_t)(b0 + cb) * TT * HH + uc;

    float cstate = 0.f;

    // ks==2: persistent registers for k in [176,192)
    ulonglong2 wper[16];
    if (ks == 2) {
#pragma unroll
        for (int j = 0; j < 16; j++)
            wper[j] = *(const ulonglong2*)((const char*)(rw + (size_t)(176 + j) * HH + ug));
    }
    // ks==3: streaming double buffer, chunk 0 persistent-reloaded
    ulonglong2 wreg[2][8];
    if (ks == 3) {
#pragma unroll
        for (int j = 0; j < 8; j++)
            wreg[0][j] = *(const ulonglong2*)(wp_g + (size_t)j * 4096);
    }

    for (int t = 0; t < TT; t++) {
        const int rb = t & 1;

        float xv0 = xc[uc];
        float xv1 = xc[HH + uc];
        float xv2 = xc[2 * HH + uc];
        float xv3 = xc[3 * HH + uc];

        unsigned long long aif[4], aco[4];
#pragma unroll
        for (int b2 = 0; b2 < 4; b2++) { aif[b2] = 0ull; aco[b2] = 0ull; }

        const char* hq = h2 + rb * (K2_H2SZ / 2) + (ks * 64) * 32;

        if (ks < 2) {
#pragma unroll 8
            for (int kk = 0; kk < 64; kk++) {
                ulonglong2 wv = *(const ulonglong2*)(wp_s + (size_t)kk * 1024);
                const char* hh = hq + kk * 32;
                ulonglong2 h01 = *(const ulonglong2*)(hh);
                ulonglong2 h23 = *(const ulonglong2*)(hh + 16);
                ffma2(aif[0], wv.x, h01.x); ffma2(aco[0], wv.y, h01.x);
                ffma2(aif[1], wv.x, h01.y); ffma2(aco[1], wv.y, h01.y);
                ffma2(aif[2], wv.x, h23.x); ffma2(aco[2], wv.y, h23.x);
                ffma2(aif[3], wv.x, h23.y); ffma2(aco[3], wv.y, h23.y);
            }
        } else if (ks == 2) {
#pragma unroll 8
            for (int kk = 0; kk < 48; kk++) {           // k 128..175 from smem
                ulonglong2 wv = *(const ulonglong2*)(wp_s + (size_t)kk * 1024);
                const char* hh = hq + kk * 32;
                ulonglong2 h01 = *(const ulonglong2*)(hh);
                ulonglong2 h23 = *(const ulonglong2*)(hh + 16);
                ffma2(aif[0], wv.x, h01.x); ffma2(aco[0], wv.y, h01.x);
                ffma2(aif[1], wv.x, h01.y); ffma2(aco[1], wv.y, h01.y);
                ffma2(aif[2], wv.x, h23.x); ffma2(aco[2], wv.y, h23.x);
                ffma2(aif[3], wv.x, h23.y); ffma2(aco[3], wv.y, h23.y);
            }
#pragma unroll
            for (int j = 0; j < 16; j++) {              // k 176..191 from regs
                ulonglong2 wv = wper[j];
                const char* hh = hq + (48 + j) * 32;
                ulonglong2 h01 = *(const ulonglong2*)(hh);
                ulonglong2 h23 = *(const ulonglong2*)(hh + 16);
                ffma2(aif[0], wv.x, h01.x); ffma2(aco[0], wv.y, h01.x);
                ffma2(aif[1], wv.x, h01.y); ffma2(aco[1], wv.y, h01.y);
                ffma2(aif[2], wv.x, h23.x); ffma2(aco[2], wv.y, h23.x);
                ffma2(aif[3], wv.x, h23.y); ffma2(aco[3], wv.y, h23.y);
            }
        } else {
#pragma unroll
            for (int ch = 0; ch < 8; ch++) {            // k 192..255 streamed
                if (ch < 7) {
#pragma unroll
                    for (int j = 0; j < 8; j++)
                        wreg[(ch + 1) & 1][j] =
                            *(const ulonglong2*)(wp_g + (size_t)((ch + 1) * 8 + j) * 4096);
                }
#pragma unroll
                for (int j = 0; j < 8; j++) {
                    const int kk = ch * 8 + j;
                    ulonglong2 wv = wreg[ch & 1][j];
                    const char* hh = hq + kk * 32;
                    ulonglong2 h01 = *(const ulonglong2*)(hh);
                    ulonglong2 h23 = *(const ulonglong2*)(hh + 16);
                    ffma2(aif[0], wv.x, h01.x); ffma2(aco[0], wv.y, h01.x);
                    ffma2(aif[1], wv.x, h01.y); ffma2(aco[1], wv.y, h01.y);
                    ffma2(aif[2], wv.x, h23.x); ffma2(aco[2], wv.y, h23.x);
                    ffma2(aif[3], wv.x, h23.y); ffma2(aco[3], wv.y, h23.y);
                }
            }
        }

        // publish partials
#pragma unroll
        for (int b2 = 0; b2 < 4; b2++)
            *(ulonglong2*)(part + (size_t)((b2 * 4 + ks) * 64 + ul) * 16) =
                make_ulonglong2(aif[b2], aco[b2]);

        // reload streaming chunk 0 — overlaps sync + cell + barrier
        if (ks == 3) {
#pragma unroll
            for (int j = 0; j < 8; j++)
                wreg[0][j] = *(const ulonglong2*)(wp_g + (size_t)j * 4096);
        }
        __syncthreads();

        // cell phase
        unsigned long long sif = 0ull, sco = 0ull;
#pragma unroll
        for (int kq = 0; kq < 4; kq++) {
            ulonglong2 p = *(const ulonglong2*)(part + (size_t)((cb * 4 + kq) * 64 + cu) * 16);
            sif = addx2(sif, p.x);
            sco = addx2(sco, p.y);
        }
        float zi = lof(sif), zf = hif(sif), zc = lof(sco), zo = hif(sco);

        float ig = fsig(zi + xv0 + cstate * wci);
        float fg = fsig(zf + xv1 + cstate * wcf);
        float cn = fg * cstate + ig * ftanh(zc + xv2);
        float og = fsig(zo + xv3 + cn * wco);
        float hn = og * ftanh(cn);
        cstate = cn;

        unsigned long long hdup;
        asm("mov.b64 %0, {%1, %1};" : "=l"(hdup) : "r"(__float_as_uint(hn)));
        const uint32_t wboff = (uint32_t)((rb ^ 1) * (K2_H2SZ / 2));
#pragma unroll
        for (int r2 = 0; r2 < K2_CLU; r2++)
            asm volatile("st.shared::cluster.b64 [%0], %1;"
                         :: "r"(rem[r2] + wboff), "l"(hdup) : "memory");

        hc[0] = hn;
        hc += HH;
        xc += NG;

        asm volatile("barrier.cluster.arrive.aligned;" ::: "memory");
        asm volatile("barrier.cluster.wait.aligned;"   ::: "memory");
    }
}

// ---------------------------------------------------------------------------
// K3: BN(inference) -> tanh -> dense head.
// ---------------------------------------------------------------------------
__global__ __launch_bounds__(256)
void head_kernel(const float* __restrict__ hs,
                 const float* __restrict__ gamma,
                 const float* __restrict__ beta,
                 const float* __restrict__ mean,
                 const float* __restrict__ var,
                 const float* __restrict__ fc,
                 float* __restrict__ out)
{
    const int warp = (blockIdx.x * blockDim.x + threadIdx.x) >> 5;
    const int lane = threadIdx.x & 31;
    if (warp >= BB * TT) return;

    const float* hrow = hs + (size_t)warp * HH;
    float acc[CC];
#pragma unroll
    for (int c = 0; c < CC; c++) acc[c] = 0.f;

#pragma unroll
    for (int kk = 0; kk < HH / 32; kk++) {
        int k = kk * 32 + lane;
        float s = rsqrtf(var[k] + BN_EPS) * gamma[k];
        float v = tanhf((hrow[k] - mean[k]) * s + beta[k]);
#pragma unroll
        for (int c = 0; c < CC; c++)
            acc[c] += v * fc[k * CC + c];
    }
#pragma unroll
    for (int c = 0; c < CC; c++) {
#pragma unroll
        for (int off = 16; off > 0; off >>= 1)
            acc[c] += __shfl_xor_sync(0xffffffffu, acc[c], off);
    }
    if (lane == 0) {
        float* orow = out + (size_t)warp * CC;
#pragma unroll
        for (int c = 0; c < CC; c++) orow[c] = acc[c];
    }
}

// ---------------------------------------------------------------------------
extern "C" void kernel_launch(void* const* d_in, const int* in_sizes, int n_in,
                              void* d_out, int out_size)
{
    const float* x      = (const float*)d_in[0];
    const float* kernel = (const float*)d_in[1];
    const float* rec    = (const float*)d_in[2];
    const float* bias   = (const float*)d_in[3];
    const float* w_ci   = (const float*)d_in[4];
    const float* w_cf   = (const float*)d_in[5];
    const float* w_co   = (const float*)d_in[6];
    const float* gamma  = (const float*)d_in[7];
    const float* beta   = (const float*)d_in[8];
    const float* mmean  = (const float*)d_in[9];
    const float* mvar   = (const float*)d_in[10];
    const float* fc_w   = (const float*)d_in[11];
    float* out = (float*)d_out;

    float*  xw_p;
    float*  hs_p;
    float4* rw_p;
    cudaGetSymbolAddress((void**)&xw_p, g_xw);
    cudaGetSymbolAddress((void**)&hs_p, g_hs);
    cudaGetSymbolAddress((void**)&rw_p, g_rw);

    cudaFuncSetAttribute(gemm_mma_kernel,
                         cudaFuncAttributeMaxDynamicSharedMemorySize, K1_SMEM);
    cudaFuncSetAttribute(lstm_hyb_kernel,
                         cudaFuncAttributeMaxDynamicSharedMemorySize, K2_SMEM);

    // K0: packing
    pack_rec_kernel<<<(HH * HH + 255) / 256, 256>>>(rec, rw_p);
    pack_b_kernel<<<((size_t)NG * FF + 255) / 256, 256>>>(kernel);
    pack_a_kernel<<<(unsigned)(((size_t)BB * TT * FF + 255) / 256), 256>>>(x);

    // K1: cp.async-pipelined HMMA GEMM, term-major MMA ordering
    dim3 g1(NG / 128, (BB * TT) / 128);
    gemm_mma_kernel<<<g1, 256, K1_SMEM>>>(bias);

    // K2: recurrence — exact R12 version (three-tier weight residency)
    lstm_hyb_kernel<<<(BB / K2_BATCH) * K2_CLU, 256, K2_SMEM>>>(
        xw_p, rw_p, w_ci, w_cf, w_co, hs_p);

    // K3: head
    int rows = BB * TT;
    head_kernel<<<(rows * 32 + 255) / 256, 256>>>(hs_p, gamma, beta, mmean, mvar, fc_w, out);
}

// round 16
// speedup vs baseline: 2.8124x; 1.1069x over previous
#include <cuda_runtime.h>
#include <cuda_fp16.h>
#include <math.h>
#include <stdint.h>

// Problem dims
#define BB   128
#define TT   512
#define FF   784
#define HH   256
#define NG   1024   // 4*H
#define CC   10
#define BN_EPS 1e-3f

// K1 GEMM tiling
#define BKC  16
#define NCHK (FF / BKC)   // 49

// Scratch (device globals; no runtime allocation allowed)
__device__ float  g_xw[(size_t)BB * TT * NG];    // 256 MiB
__device__ float  g_hs[(size_t)BB * TT * HH];    //  64 MiB
__device__ float4 g_rw[(size_t)HH * HH];         //   1 MiB packed rec weights {i,f,c,o}
__device__ __half g_bhi[(size_t)NG * FF];        // 1.6 MiB: kernel^T hi [n][k] fp16
__device__ __half g_blo[(size_t)NG * FF];        // 1.6 MiB: kernel^T lo
__device__ __half g_ah [(size_t)BB * TT * FF];   //  98 MiB: x fp16 [m][k]

// ---------------------------------------------------------------------------
// helpers
// ---------------------------------------------------------------------------
__device__ __forceinline__ uint32_t smem_u32(const void* p) {
    uint32_t a;
    asm("{ .reg .u64 t; cvta.to.shared.u64 t, %1; cvt.u32.u64 %0, t; }" : "=r"(a) : "l"(p));
    return a;
}
__device__ __forceinline__ float fsig(float x) {
    return __fdividef(1.f, 1.f + __expf(-x));
}
__device__ __forceinline__ float ftanh(float x) {
    x = fminf(fmaxf(x, -15.f), 15.f);
    float e = __expf(-2.f * x);
    return __fdividef(1.f - e, 1.f + e);
}
__device__ __forceinline__ void mma_f16(float* d, const uint32_t* a, const uint32_t* b) {
    asm volatile(
        "mma.sync.aligned.m16n8k16.row.col.f32.f16.f16.f32 "
        "{%0,%1,%2,%3}, {%4,%5,%6,%7}, {%8,%9}, {%0,%1,%2,%3};"
        : "+f"(d[0]), "+f"(d[1]), "+f"(d[2]), "+f"(d[3])
        : "r"(a[0]), "r"(a[1]), "r"(a[2]), "r"(a[3]), "r"(b[0]), "r"(b[1]));
}
__device__ __forceinline__ void ldsm4(uint32_t* r, uint32_t a) {
    asm volatile("ldmatrix.sync.aligned.m8n8.x4.shared.b16 {%0,%1,%2,%3}, [%4];"
                 : "=r"(r[0]), "=r"(r[1]), "=r"(r[2]), "=r"(r[3]) : "r"(a));
}
// packed fp32x2 (B300 FFMA2)
__device__ __forceinline__ void ffma2(unsigned long long& d,
                                      unsigned long long a, unsigned long long b) {
    asm("fma.rn.f32x2 %0, %1, %2, %0;" : "+l"(d) : "l"(a), "l"(b));
}
__device__ __forceinline__ unsigned long long addx2(unsigned long long a,
                                                    unsigned long long b) {
    unsigned long long d;
    asm("add.rn.f32x2 %0, %1, %2;" : "=l"(d) : "l"(a), "l"(b));
    return d;
}
__device__ __forceinline__ float lof(unsigned long long v) {
    return __uint_as_float((uint32_t)v);
}
__device__ __forceinline__ float hif(unsigned long long v) {
    return __uint_as_float((uint32_t)(v >> 32));
}
__device__ __forceinline__ void cp16(uint32_t dst, const void* src) {
    asm volatile("cp.async.cg.shared.global [%0], [%1], 16;" :: "r"(dst), "l"(src));
}
#define CP_COMMIT() asm volatile("cp.async.commit_group;" ::: "memory")
#define CP_WAIT2()  asm volatile("cp.async.wait_group 2;"  ::: "memory")

// ---------------------------------------------------------------------------
// K0a: pack rec_kernel [H,4H] -> rw[k][u] float4 {i,f,c,o}
// ---------------------------------------------------------------------------
__global__ void pack_rec_kernel(const float* __restrict__ rec, float4* __restrict__ rw)
{
    int idx = blockIdx.x * blockDim.x + threadIdx.x;
    if (idx >= HH * HH) return;
    int k = idx >> 8;
    int u = idx & 255;
    const float* r = rec + (size_t)k * NG;
    rw[idx] = make_float4(r[u], r[HH + u], r[2 * HH + u], r[3 * HH + u]);
}

// ---------------------------------------------------------------------------
// K0b: split + transpose kernel [F,4H] -> g_bhi/g_blo [n][k] fp16 hi/lo
// ---------------------------------------------------------------------------
__global__ void pack_b_kernel(const float* __restrict__ Bm)
{
    int idx = blockIdx.x * blockDim.x + threadIdx.x;
    if (idx >= NG * FF) return;
    int n = idx / FF;
    int k = idx % FF;
    float v = Bm[(size_t)k * NG + n];
    __half h = __float2half(v);
    __half l = __float2half(v - __half2float(h));
    g_bhi[idx] = h;
    g_blo[idx] = l;
}

// ---------------------------------------------------------------------------
// K0c: x [m][k] fp32 -> g_ah fp16 (single term: fp16 ~2^-12 relative error)
// ---------------------------------------------------------------------------
__global__ void pack_a_kernel(const float* __restrict__ x)
{
    size_t idx = (size_t)blockIdx.x * blockDim.x + threadIdx.x;
    if (idx >= (size_t)BB * TT * FF) return;
    g_ah[idx] = __float2half(x[idx]);
}

// ---------------------------------------------------------------------------
// K1: xw = x @ kernel + bias via mma.sync fp16x2: a_hi*(b_hi + b_lo).
// Pre-packed fp16 A/B, 4-stage cp.async pipeline, ldmatrix.x4 fragments.
// 2 MMAs per accumulator per chunk (was 3 with bf16x3).
// smem/stage: Ah 6K | Bh 6K | Bl 6K = 18 KB; 4 stages = 72 KB.
// ---------------------------------------------------------------------------
#define SROW 48
#define K1_STAGE_BYTES (3 * 128 * SROW)              // 18432
#define K1_SMEM (4 * K1_STAGE_BYTES)                 // 73728

__global__ __launch_bounds__(256, 2)
void gemm_mma_kernel(const float* __restrict__ bias)
{
    extern __shared__ __align__(16) char smk[];
    const uint32_t sbase = smem_u32(smk);

    const int tid  = threadIdx.x;
    const int lane = tid & 31;
    const int wid  = tid >> 5;
    const int bx   = blockIdx.x;
    const int by   = blockIdx.y;

    const int m0w = (wid & 3) * 32;
    const int n0w = (wid >> 2) * 64;
    const int g   = lane >> 2;
    const int tq  = lane & 3;

    float d[2][8][4];
#pragma unroll
    for (int i = 0; i < 2; i++)
#pragma unroll
        for (int j = 0; j < 8; j++)
#pragma unroll
            for (int q = 0; q < 4; q++) d[i][j][q] = 0.f;

    const int r = tid >> 1;
    const int c = tid & 1;
    const size_t a_row_bytes = ((size_t)(by * 128 + r) * FF) * 2 + c * 16;
    const size_t b_row_bytes = ((size_t)(bx * 128 + r) * FF) * 2 + c * 16;
    const char* pAh = (const char*)g_ah  + a_row_bytes;
    const char* pBh = (const char*)g_bhi + b_row_bytes;
    const char* pBl = (const char*)g_blo + b_row_bytes;
    const uint32_t s_off = (uint32_t)(r * SROW + c * 16);

    uint32_t a_off[2], b_off[4];
#pragma unroll
    for (int i = 0; i < 2; i++)
        a_off[i] = (uint32_t)((m0w + i * 16 + (lane & 15)) * SROW + (lane >> 4) * 16);
#pragma unroll
    for (int j2 = 0; j2 < 4; j2++)
        b_off[j2] = (uint32_t)((n0w + j2 * 16 + ((lane >> 4) * 8) + (lane & 7)) * SROW
                               + ((lane >> 3) & 1) * 16);

#pragma unroll
    for (int s = 0; s < 3; s++) {
        const uint32_t sb = sbase + s * K1_STAGE_BYTES;
        const size_t gk = (size_t)s * 32;
        cp16(sb + s_off,              pAh + gk);
        cp16(sb + 6144  + s_off,      pBh + gk);
        cp16(sb + 12288 + s_off,      pBl + gk);
        CP_COMMIT();
    }

    for (int ic = 0; ic < NCHK; ic++) {
        CP_WAIT2();
        __syncthreads();

        {
            const int s = ic + 3;
            if (s < NCHK) {
                const uint32_t sb = sbase + (s & 3) * K1_STAGE_BYTES;
                const size_t gk = (size_t)s * 32;
                cp16(sb + s_off,         pAh + gk);
                cp16(sb + 6144  + s_off, pBh + gk);
                cp16(sb + 12288 + s_off, pBl + gk);
            }
            CP_COMMIT();
        }

        const uint32_t stg = sbase + (ic & 3) * K1_STAGE_BYTES;

        uint32_t ah[2][4];
#pragma unroll
        for (int i = 0; i < 2; i++)
            ldsm4(ah[i], stg + a_off[i]);

#pragma unroll
        for (int j2 = 0; j2 < 4; j2++) {
            uint32_t bh4[4], bl4[4];
            ldsm4(bh4, stg + 6144  + b_off[j2]);
            ldsm4(bl4, stg + 12288 + b_off[j2]);
#pragma unroll
            for (int jj = 0; jj < 2; jj++) {
                const int j = j2 * 2 + jj;
                uint32_t bhf[2] = {bh4[jj * 2], bh4[jj * 2 + 1]};
                uint32_t blf[2] = {bl4[jj * 2], bl4[jj * 2 + 1]};
#pragma unroll
                for (int i = 0; i < 2; i++) {
                    mma_f16(d[i][j], ah[i], bhf);
                    mma_f16(d[i][j], ah[i], blf);
                }
            }
        }
    }

#pragma unroll
    for (int j = 0; j < 8; j++) {
        const int col = bx * 128 + n0w + j * 8 + tq * 2;
        const float b0 = bias[col];
        const float b1 = bias[col + 1];
#pragma unroll
        for (int i = 0; i < 2; i++) {
            const int row = by * 128 + m0w + i * 16 + g;
            float2 v0 = make_float2(d[i][j][0] + b0, d[i][j][1] + b1);
            float2 v1 = make_float2(d[i][j][2] + b0, d[i][j][3] + b1);
            *(float2*)(g_xw + (size_t)row * NG + col)       = v0;
            *(float2*)(g_xw + (size_t)(row + 8) * NG + col) = v1;
        }
    }
}

// ---------------------------------------------------------------------------
// K2: peephole LSTM — exact R12 version (best known).
// 32 clusters x 4 CTAs (128 SMs), 4 batches/cluster, k-split-4,
// three-tier weight residency:
//   ks 0,1 : k [0,128)   smem
//   ks 2   : k [128,176) smem + k [176,192) persistent registers
//   ks 3   : k [192,256) streamed from L2 (reg double-buffer; chunk-0
//            reloaded during the cell phase)
// ---------------------------------------------------------------------------
#define K2_CLU   4
#define K2_BATCH 4
#define K2_WSB   (176 * 64 * 16)                 // 180224
#define K2_H2SZ  16384
#define K2_PART  16384
#define K2_SMEM  (K2_WSB + K2_H2SZ + K2_PART)    // 212992

__global__ __launch_bounds__(256, 1) __cluster_dims__(K2_CLU, 1, 1)
void lstm_hyb_kernel(const float*  __restrict__ xw,
                     const float4* __restrict__ rw,
                     const float*  __restrict__ wci_p,
                     const float*  __restrict__ wcf_p,
                     const float*  __restrict__ wco_p,
                     float* __restrict__ hs)
{
    extern __shared__ __align__(16) char sm2[];
    char* wsm  = sm2;                       // [k<176][64 ul] ull2
    char* h2   = sm2 + K2_WSB;              // [2][256 k][4 b] dup-ull
    char* part = sm2 + K2_WSB + K2_H2SZ;    // [4 b][4 ks][64 ul] ull2

    const int tid = threadIdx.x;
    uint32_t rank;
    asm("mov.u32 %0, %%cluster_ctarank;" : "=r"(rank));
    const int cl = blockIdx.x >> 2;
    const int b0 = cl * K2_BATCH;

    const int ks = tid >> 6;
    const int ul = tid & 63;
    const int ug = (int)rank * 64 + ul;
    const int cu = tid >> 2;
    const int cb = tid & 3;
    const int uc = (int)rank * 64 + cu;

    // stage k<176 weights
    for (int idx = tid; idx < 176 * 64; idx += 256) {
        int k  = idx >> 6;
        int uu = idx & 63;
        *(float4*)(wsm + (size_t)idx * 16) = rw[(k << 8) + (int)rank * 64 + uu];
    }
    for (int i = tid; i < 1024; i += 256)
        *(unsigned long long*)(h2 + (size_t)i * 8) = 0ull;

    const float wci = wci_p[uc];
    const float wcf = wcf_p[uc];
    const float wco = wco_p[uc];

    uint32_t rem[K2_CLU];
    {
        uint32_t l0 = smem_u32(h2) + (uint32_t)(uc * 4 + cb) * 8u;
#pragma unroll
        for (int r2 = 0; r2 < K2_CLU; r2++)
            asm("mapa.shared::cluster.u32 %0, %1, %2;"
                : "=r"(rem[r2]) : "r"(l0), "r"(r2));
    }

    __syncthreads();
    asm volatile("barrier.cluster.arrive.aligned;" ::: "memory");
    asm volatile("barrier.cluster.wait.aligned;"   ::: "memory");

    const char* wp_s = wsm + ((size_t)(ks * 64) * 64 + ul) * 16;
    const char* wp_g = (const char*)(rw + (size_t)(ks * 64) * HH + ug);
    const float* xc = xw + (size_t)(b0 + cb) * TT * NG;
    float* hc = hs + (size_t)(b0 + cb) * TT * HH + uc;

    float cstate = 0.f;

    // ks==2: persistent registers for k in [176,192)
    ulonglong2 wper[16];
    if (ks == 2) {
#pragma unroll
        for (int j = 0; j < 16; j++)
            wper[j] = *(const ulonglong2*)((const char*)(rw + (size_t)(176 + j) * HH + ug));
    }
    // ks==3: streaming double buffer, chunk 0 persistent-reloaded
    ulonglong2 wreg[2][8];
    if (ks == 3) {
#pragma unroll
        for (int j = 0; j < 8; j++)
            wreg[0][j] = *(const ulonglong2*)(wp_g + (size_t)j * 4096);
    }

    for (int t = 0; t < TT; t++) {
        const int rb = t & 1;

        float xv0 = xc[uc];
        float xv1 = xc[HH + uc];
        float xv2 = xc[2 * HH + uc];
        float xv3 = xc[3 * HH + uc];

        unsigned long long aif[4], aco[4];
#pragma unroll
        for (int b2 = 0; b2 < 4; b2++) { aif[b2] = 0ull; aco[b2] = 0ull; }

        const char* hq = h2 + rb * (K2_H2SZ / 2) + (ks * 64) * 32;

        if (ks < 2) {
#pragma unroll 8
            for (int kk = 0; kk < 64; kk++) {
                ulonglong2 wv = *(const ulonglong2*)(wp_s + (size_t)kk * 1024);
                const char* hh = hq + kk * 32;
                ulonglong2 h01 = *(const ulonglong2*)(hh);
                ulonglong2 h23 = *(const ulonglong2*)(hh + 16);
                ffma2(aif[0], wv.x, h01.x); ffma2(aco[0], wv.y, h01.x);
                ffma2(aif[1], wv.x, h01.y); ffma2(aco[1], wv.y, h01.y);
                ffma2(aif[2], wv.x, h23.x); ffma2(aco[2], wv.y, h23.x);
                ffma2(aif[3], wv.x, h23.y); ffma2(aco[3], wv.y, h23.y);
            }
        } else if (ks == 2) {
#pragma unroll 8
            for (int kk = 0; kk < 48; kk++) {           // k 128..175 from smem
                ulonglong2 wv = *(const ulonglong2*)(wp_s + (size_t)kk * 1024);
                const char* hh = hq + kk * 32;
                ulonglong2 h01 = *(const ulonglong2*)(hh);
                ulonglong2 h23 = *(const ulonglong2*)(hh + 16);
                ffma2(aif[0], wv.x, h01.x); ffma2(aco[0], wv.y, h01.x);
                ffma2(aif[1], wv.x, h01.y); ffma2(aco[1], wv.y, h01.y);
                ffma2(aif[2], wv.x, h23.x); ffma2(aco[2], wv.y, h23.x);
                ffma2(aif[3], wv.x, h23.y); ffma2(aco[3], wv.y, h23.y);
            }
#pragma unroll
            for (int j = 0; j < 16; j++) {              // k 176..191 from regs
                ulonglong2 wv = wper[j];
                const char* hh = hq + (48 + j) * 32;
                ulonglong2 h01 = *(const ulonglong2*)(hh);
                ulonglong2 h23 = *(const ulonglong2*)(hh + 16);
                ffma2(aif[0], wv.x, h01.x); ffma2(aco[0], wv.y, h01.x);
                ffma2(aif[1], wv.x, h01.y); ffma2(aco[1], wv.y, h01.y);
                ffma2(aif[2], wv.x, h23.x); ffma2(aco[2], wv.y, h23.x);
                ffma2(aif[3], wv.x, h23.y); ffma2(aco[3], wv.y, h23.y);
            }
        } else {
#pragma unroll
            for (int ch = 0; ch < 8; ch++) {            // k 192..255 streamed
                if (ch < 7) {
#pragma unroll
                    for (int j = 0; j < 8; j++)
                        wreg[(ch + 1) & 1][j] =
                            *(const ulonglong2*)(wp_g + (size_t)((ch + 1) * 8 + j) * 4096);
                }
#pragma unroll
                for (int j = 0; j < 8; j++) {
                    const int kk = ch * 8 + j;
                    ulonglong2 wv = wreg[ch & 1][j];
                    const char* hh = hq + kk * 32;
                    ulonglong2 h01 = *(const ulonglong2*)(hh);
                    ulonglong2 h23 = *(const ulonglong2*)(hh + 16);
                    ffma2(aif[0], wv.x, h01.x); ffma2(aco[0], wv.y, h01.x);
                    ffma2(aif[1], wv.x, h01.y); ffma2(aco[1], wv.y, h01.y);
                    ffma2(aif[2], wv.x, h23.x); ffma2(aco[2], wv.y, h23.x);
                    ffma2(aif[3], wv.x, h23.y); ffma2(aco[3], wv.y, h23.y);
                }
            }
        }

        // publish partials
#pragma unroll
        for (int b2 = 0; b2 < 4; b2++)
            *(ulonglong2*)(part + (size_t)((b2 * 4 + ks) * 64 + ul) * 16) =
                make_ulonglong2(aif[b2], aco[b2]);

        // reload streaming chunk 0 — overlaps sync + cell + barrier
        if (ks == 3) {
#pragma unroll
            for (int j = 0; j < 8; j++)
                wreg[0][j] = *(const ulonglong2*)(wp_g + (size_t)j * 4096);
        }
        __syncthreads();

        // cell phase
        unsigned long long sif = 0ull, sco = 0ull;
#pragma unroll
        for (int kq = 0; kq < 4; kq++) {
            ulonglong2 p = *(const ulonglong2*)(part + (size_t)((cb * 4 + kq) * 64 + cu) * 16);
            sif = addx2(sif, p.x);
            sco = addx2(sco, p.y);
        }
        float zi = lof(sif), zf = hif(sif), zc = lof(sco), zo = hif(sco);

        float ig = fsig(zi + xv0 + cstate * wci);
        float fg = fsig(zf + xv1 + cstate * wcf);
        float cn = fg * cstate + ig * ftanh(zc + xv2);
        float og = fsig(zo + xv3 + cn * wco);
        float hn = og * ftanh(cn);
        cstate = cn;

        unsigned long long hdup;
        asm("mov.b64 %0, {%1, %1};" : "=l"(hdup) : "r"(__float_as_uint(hn)));
        const uint32_t wboff = (uint32_t)((rb ^ 1) * (K2_H2SZ / 2));
#pragma unroll
        for (int r2 = 0; r2 < K2_CLU; r2++)
            asm volatile("st.shared::cluster.b64 [%0], %1;"
                         :: "r"(rem[r2] + wboff), "l"(hdup) : "memory");

        hc[0] = hn;
        hc += HH;
        xc += NG;

        asm volatile("barrier.cluster.arrive.aligned;" ::: "memory");
        asm volatile("barrier.cluster.wait.aligned;"   ::: "memory");
    }
}

// ---------------------------------------------------------------------------
// K3: BN(inference) -> tanh -> dense head.
// ---------------------------------------------------------------------------
__global__ __launch_bounds__(256)
void head_kernel(const float* __restrict__ hs,
                 const float* __restrict__ gamma,
                 const float* __restrict__ beta,
                 const float* __restrict__ mean,
                 const float* __restrict__ var,
                 const float* __restrict__ fc,
                 float* __restrict__ out)
{
    const int warp = (blockIdx.x * blockDim.x + threadIdx.x) >> 5;
    const int lane = threadIdx.x & 31;
    if (warp >= BB * TT) return;

    const float* hrow = hs + (size_t)warp * HH;
    float acc[CC];
#pragma unroll
    for (int c = 0; c < CC; c++) acc[c] = 0.f;

#pragma unroll
    for (int kk = 0; kk < HH / 32; kk++) {
        int k = kk * 32 + lane;
        float s = rsqrtf(var[k] + BN_EPS) * gamma[k];
        float v = tanhf((hrow[k] - mean[k]) * s + beta[k]);
#pragma unroll
        for (int c = 0; c < CC; c++)
            acc[c] += v * fc[k * CC + c];
    }
#pragma unroll
    for (int c = 0; c < CC; c++) {
#pragma unroll
        for (int off = 16; off > 0; off >>= 1)
            acc[c] += __shfl_xor_sync(0xffffffffu, acc[c], off);
    }
    if (lane == 0) {
        float* orow = out + (size_t)warp * CC;
#pragma unroll
        for (int c = 0; c < CC; c++) orow[c] = acc[c];
    }
}

// ---------------------------------------------------------------------------
extern "C" void kernel_launch(void* const* d_in, const int* in_sizes, int n_in,
                              void* d_out, int out_size)
{
    const float* x      = (const float*)d_in[0];
    const float* kernel = (const float*)d_in[1];
    const float* rec    = (const float*)d_in[2];
    const float* bias   = (const float*)d_in[3];
    const float* w_ci   = (const float*)d_in[4];
    const float* w_cf   = (const float*)d_in[5];
    const float* w_co   = (const float*)d_in[6];
    const float* gamma  = (const float*)d_in[7];
    const float* beta   = (const float*)d_in[8];
    const float* mmean  = (const float*)d_in[9];
    const float* mvar   = (const float*)d_in[10];
    const float* fc_w   = (const float*)d_in[11];
    float* out = (float*)d_out;

    float*  xw_p;
    float*  hs_p;
    float4* rw_p;
    cudaGetSymbolAddress((void**)&xw_p, g_xw);
    cudaGetSymbolAddress((void**)&hs_p, g_hs);
    cudaGetSymbolAddress((void**)&rw_p, g_rw);

    cudaFuncSetAttribute(gemm_mma_kernel,
                         cudaFuncAttributeMaxDynamicSharedMemorySize, K1_SMEM);
    cudaFuncSetAttribute(lstm_hyb_kernel,
                         cudaFuncAttributeMaxDynamicSharedMemorySize, K2_SMEM);

    // K0: packing
    pack_rec_kernel<<<(HH * HH + 255) / 256, 256>>>(rec, rw_p);
    pack_b_kernel<<<((size_t)NG * FF + 255) / 256, 256>>>(kernel);
    pack_a_kernel<<<(unsigned)(((size_t)BB * TT * FF + 255) / 256), 256>>>(x);

    // K1: cp.async-pipelined fp16x2 HMMA GEMM
    dim3 g1(NG / 128, (BB * TT) / 128);
    gemm_mma_kernel<<<g1, 256, K1_SMEM>>>(bias);

    // K2: recurrence — R12 version (three-tier weight residency)
    lstm_hyb_kernel<<<(BB / K2_BATCH) * K2_CLU, 256, K2_SMEM>>>(
        xw_p, rw_p, w_ci, w_cf, w_co, hs_p);

    // K3: head
    int rows = BB * TT;
    head_kernel<<<(rows * 32 + 255) / 256, 256>>>(hs_p, gamma, beta, mmean, mvar, fc_w, out);
}